// round 1
// baseline (speedup 1.0000x reference)
#include <cuda_runtime.h>
#include <math.h>

#define Tt 4096
#define Dd 1024
#define Hh 4096
#define Ee 8
#define Kk 2

// ---------------- device scratch (no allocations allowed) ----------------
__device__ int   g_cnt[Ee];                       // tokens per expert
__device__ int   g_slot[Ee * Tt];                 // slot (= t*2+k) list per expert
__device__ float g_wt[Tt * Kk];                   // combine weight per slot
__device__ float g_probs[Tt * Ee];                // full softmax probs (for loss)
__device__ float g_h[(size_t)Tt * Kk * Hh];       // gelu(x@w1+b1) per slot, 128MB
__device__ float g_y[(size_t)Tt * Kk * Dd];       // (h@w2+b2) per slot, 32MB

// ---------------- zero counters ----------------
__global__ void zero_kernel() {
    int i = threadIdx.x;
    if (i < Ee) g_cnt[i] = 0;
}

// ---------------- router: 1 warp per token ----------------
__global__ void router_kernel(const float* __restrict__ x,
                              const float* __restrict__ rw) {
    int tid  = threadIdx.x;
    int warp = tid >> 5, lane = tid & 31;
    int t = blockIdx.x * 8 + warp;          // 512 blocks * 8 warps = 4096 tokens

    const float* xr = x + (size_t)t * Dd;
    float acc[Ee];
#pragma unroll
    for (int e = 0; e < Ee; e++) acc[e] = 0.f;

    for (int d = lane; d < Dd; d += 32) {
        float xv = xr[d];
#pragma unroll
        for (int e = 0; e < Ee; e++) acc[e] += xv * rw[e * Dd + d];
    }
#pragma unroll
    for (int e = 0; e < Ee; e++) {
#pragma unroll
        for (int off = 16; off > 0; off >>= 1)
            acc[e] += __shfl_xor_sync(0xffffffffu, acc[e], off);
    }

    if (lane == 0) {
        float mx = acc[0];
#pragma unroll
        for (int e = 1; e < Ee; e++) mx = fmaxf(mx, acc[e]);
        float pe[Ee], s = 0.f;
#pragma unroll
        for (int e = 0; e < Ee; e++) { pe[e] = __expf(acc[e] - mx); s += pe[e]; }
        float inv = 1.f / s;
#pragma unroll
        for (int e = 0; e < Ee; e++) {
            pe[e] *= inv;
            g_probs[t * Ee + e] = pe[e];
        }
        // top-2 (strict > keeps lowest index on ties, matching lax.top_k)
        int i1 = 0;
#pragma unroll
        for (int e = 1; e < Ee; e++) if (pe[e] > pe[i1]) i1 = e;
        int i2 = (i1 == 0) ? 1 : 0;
#pragma unroll
        for (int e = 0; e < Ee; e++) if (e != i1 && pe[e] > pe[i2]) i2 = e;
        float denom = pe[i1] + pe[i2] + 1e-8f;
        float wa = pe[i1] / denom, wb = pe[i2] / denom;

        int p1 = atomicAdd(&g_cnt[i1], 1);
        g_slot[i1 * Tt + p1] = t * 2 + 0;
        g_wt[t * 2 + 0] = wa;
        int p2 = atomicAdd(&g_cnt[i2], 1);
        g_slot[i2 * Tt + p2] = t * 2 + 1;
        g_wt[t * 2 + 1] = wb;
    }
}

// ---------------- GEMM1: h[slot] = gelu(x[tok] @ w1[e] + b1[e]) ----------------
// tile 128x128, K-step 8, 256 threads, 8x8 micro-tile, gathered A rows
__global__ __launch_bounds__(256)
void gemm1_kernel(const float* __restrict__ x,
                  const float* __restrict__ w1,
                  const float* __restrict__ b1) {
    const int e   = blockIdx.z;
    const int ne  = g_cnt[e];
    const int row0 = blockIdx.x * 128;
    if (row0 >= ne) return;
    const int n0 = blockIdx.y * 128;

    __shared__ float As[8][128];
    __shared__ float Bs[8][128];
    __shared__ int   s_slot[128];

    const int tid = threadIdx.x;
    if (tid < 128) {
        int r = row0 + tid;
        s_slot[tid] = (r < ne) ? g_slot[e * Tt + r] : -1;
    }
    __syncthreads();

    const int arow = tid >> 1;
    const int aq   = (tid & 1) * 4;
    int sa = s_slot[arow];
    const float* aptr = x + (size_t)((sa < 0) ? 0 : (sa >> 1)) * Dd + aq;

    const int bk = tid >> 5;
    const int bn = (tid & 31) * 4;
    const float* bptr = w1 + (size_t)e * Dd * Hh + (size_t)bk * Hh + n0 + bn;

    const int tr = (tid >> 4) * 8;
    const int tc = (tid & 15) * 8;

    float acc[8][8];
#pragma unroll
    for (int i = 0; i < 8; i++)
#pragma unroll
        for (int j = 0; j < 8; j++) acc[i][j] = 0.f;

    float4 av = *(const float4*)(aptr);
    float4 bv = *(const float4*)(bptr);

    for (int k0 = 0; k0 < Dd; k0 += 8) {
        As[aq + 0][arow] = av.x; As[aq + 1][arow] = av.y;
        As[aq + 2][arow] = av.z; As[aq + 3][arow] = av.w;
        *(float4*)&Bs[bk][bn] = bv;
        __syncthreads();
        if (k0 + 8 < Dd) {
            av = *(const float4*)(aptr + k0 + 8);
            bv = *(const float4*)(bptr + (size_t)(k0 + 8) * Hh);
        }
#pragma unroll
        for (int kk = 0; kk < 8; kk++) {
            float a[8], b[8];
            *(float4*)(a)     = *(const float4*)&As[kk][tr];
            *(float4*)(a + 4) = *(const float4*)&As[kk][tr + 4];
            *(float4*)(b)     = *(const float4*)&Bs[kk][tc];
            *(float4*)(b + 4) = *(const float4*)&Bs[kk][tc + 4];
#pragma unroll
            for (int i = 0; i < 8; i++)
#pragma unroll
                for (int j = 0; j < 8; j++) acc[i][j] += a[i] * b[j];
        }
        __syncthreads();
    }

    float bb[8];
#pragma unroll
    for (int j = 0; j < 8; j++) bb[j] = b1[e * Hh + n0 + tc + j];

#pragma unroll
    for (int i = 0; i < 8; i++) {
        int s = s_slot[tr + i];
        if (s < 0) continue;
        float* hrow = g_h + (size_t)s * Hh + n0 + tc;
        float vals[8];
#pragma unroll
        for (int j = 0; j < 8; j++) {
            float v = acc[i][j] + bb[j];
            vals[j] = 0.5f * v * (1.f + erff(v * 0.70710678118654752440f));
        }
        *(float4*)(hrow)     = *(float4*)(vals);
        *(float4*)(hrow + 4) = *(float4*)(vals + 4);
    }
}

// ---------------- GEMM2: y[slot] = h[slot] @ w2[e] + b2[e] ----------------
__global__ __launch_bounds__(256)
void gemm2_kernel(const float* __restrict__ w2,
                  const float* __restrict__ b2) {
    const int e   = blockIdx.z;
    const int ne  = g_cnt[e];
    const int row0 = blockIdx.x * 128;
    if (row0 >= ne) return;
    const int n0 = blockIdx.y * 128;

    __shared__ float As[8][128];
    __shared__ float Bs[8][128];
    __shared__ int   s_slot[128];

    const int tid = threadIdx.x;
    if (tid < 128) {
        int r = row0 + tid;
        s_slot[tid] = (r < ne) ? g_slot[e * Tt + r] : -1;
    }
    __syncthreads();

    const int arow = tid >> 1;
    const int aq   = (tid & 1) * 4;
    int sa = s_slot[arow];
    const float* aptr = g_h + (size_t)((sa < 0) ? 0 : sa) * Hh + aq;

    const int bk = tid >> 5;
    const int bn = (tid & 31) * 4;
    const float* bptr = w2 + (size_t)e * Hh * Dd + (size_t)bk * Dd + n0 + bn;

    const int tr = (tid >> 4) * 8;
    const int tc = (tid & 15) * 8;

    float acc[8][8];
#pragma unroll
    for (int i = 0; i < 8; i++)
#pragma unroll
        for (int j = 0; j < 8; j++) acc[i][j] = 0.f;

    float4 av = *(const float4*)(aptr);
    float4 bv = *(const float4*)(bptr);

    for (int k0 = 0; k0 < Hh; k0 += 8) {
        As[aq + 0][arow] = av.x; As[aq + 1][arow] = av.y;
        As[aq + 2][arow] = av.z; As[aq + 3][arow] = av.w;
        *(float4*)&Bs[bk][bn] = bv;
        __syncthreads();
        if (k0 + 8 < Hh) {
            av = *(const float4*)(aptr + k0 + 8);
            bv = *(const float4*)(bptr + (size_t)(k0 + 8) * Dd);
        }
#pragma unroll
        for (int kk = 0; kk < 8; kk++) {
            float a[8], b[8];
            *(float4*)(a)     = *(const float4*)&As[kk][tr];
            *(float4*)(a + 4) = *(const float4*)&As[kk][tr + 4];
            *(float4*)(b)     = *(const float4*)&Bs[kk][tc];
            *(float4*)(b + 4) = *(const float4*)&Bs[kk][tc + 4];
#pragma unroll
            for (int i = 0; i < 8; i++)
#pragma unroll
                for (int j = 0; j < 8; j++) acc[i][j] += a[i] * b[j];
        }
        __syncthreads();
    }

    float bb[8];
#pragma unroll
    for (int j = 0; j < 8; j++) bb[j] = b2[e * Dd + n0 + tc + j];

#pragma unroll
    for (int i = 0; i < 8; i++) {
        int s = s_slot[tr + i];
        if (s < 0) continue;
        float* yrow = g_y + (size_t)s * Dd + n0 + tc;
        float vals[8];
#pragma unroll
        for (int j = 0; j < 8; j++) vals[j] = acc[i][j] + bb[j];
        *(float4*)(yrow)     = *(float4*)(vals);
        *(float4*)(yrow + 4) = *(float4*)(vals + 4);
    }
}

// ---------------- combine: out[t] = w0*y[2t] + w1*y[2t+1] ----------------
__global__ void combine_kernel(float* __restrict__ out) {
    int i = blockIdx.x * blockDim.x + threadIdx.x;   // over T*D/4 float4
    int t  = i >> 8;                                 // D/4 = 256
    int d4 = i & 255;
    float w0 = g_wt[2 * t], w1 = g_wt[2 * t + 1];
    const float4* y = (const float4*)g_y;
    float4 a = y[(size_t)(2 * t) * 256 + d4];
    float4 b = y[(size_t)(2 * t + 1) * 256 + d4];
    float4 o;
    o.x = w0 * a.x + w1 * b.x;
    o.y = w0 * a.y + w1 * b.y;
    o.z = w0 * a.z + w1 * b.z;
    o.w = w0 * a.w + w1 * b.w;
    ((float4*)out)[i] = o;
}

// ---------------- load-balancing loss (deterministic reduction) ----------------
__global__ void loss_kernel(float* __restrict__ out, int write_loss) {
    __shared__ float sred[256 * Ee];
    int tid = threadIdx.x;
    float l[Ee];
#pragma unroll
    for (int e = 0; e < Ee; e++) l[e] = 0.f;
    for (int t = tid; t < Tt; t += 256)
#pragma unroll
        for (int e = 0; e < Ee; e++) l[e] += g_probs[t * Ee + e];
#pragma unroll
    for (int e = 0; e < Ee; e++) sred[tid * Ee + e] = l[e];
    __syncthreads();
    for (int s = 128; s > 0; s >>= 1) {
        if (tid < s)
#pragma unroll
            for (int e = 0; e < Ee; e++)
                sred[tid * Ee + e] += sred[(tid + s) * Ee + e];
        __syncthreads();
    }
    if (tid == 0 && write_loss) {
        float loss = 0.f;
        for (int e = 0; e < Ee; e++) {
            float mean_p = sred[e] / (float)Tt;
            float frac   = (float)g_cnt[e] / (float)(Tt * Kk);
            loss += mean_p * frac;
        }
        out[(size_t)Tt * Dd] = loss * (float)Ee;
    }
}

// ---------------- launch ----------------
extern "C" void kernel_launch(void* const* d_in, const int* in_sizes, int n_in,
                              void* d_out, int out_size) {
    const float* x   = (const float*)d_in[0];
    const float* rw  = (const float*)d_in[1];
    const float* w1  = (const float*)d_in[2];
    const float* b1  = (const float*)d_in[3];
    const float* w2  = (const float*)d_in[4];
    const float* b2  = (const float*)d_in[5];
    float* out = (float*)d_out;

    zero_kernel<<<1, 32>>>();
    router_kernel<<<Tt / 8, 256>>>(x, rw);

    dim3 g1(Tt / 128, Hh / 128, Ee);
    gemm1_kernel<<<g1, 256>>>(x, w1, b1);

    dim3 g2(Tt / 128, Dd / 128, Ee);
    gemm2_kernel<<<g2, 256>>>(w2, b2);

    combine_kernel<<<(Tt * Dd / 4) / 256, 256>>>(out);

    int write_loss = (out_size > Tt * Dd) ? 1 : 0;
    loss_kernel<<<1, 256>>>(out, write_loss);
}

// round 8
// speedup vs baseline: 2.1634x; 2.1634x over previous
#include <cuda_runtime.h>
#include <math.h>

#define Tt 4096
#define Dd 1024
#define Hh 4096
#define Ee 8
#define Kk 2

// ---------------- device scratch ----------------
__device__ int   g_cnt[Ee];
__device__ int   g_slot[Ee * Tt];
__device__ float g_wt[Tt * Kk];
__device__ float g_probs[Tt * Ee];
__device__ float g_h[(size_t)Tt * Kk * Hh];     // gelu(x@w1+b1) per slot
__device__ float g_y[(size_t)Tt * Kk * Dd];     // (h@w2+b2) per slot

// ---------------- helpers ----------------
__device__ __forceinline__ unsigned smem_u32(const void* p) {
    unsigned a;
    asm("{ .reg .u64 t; cvta.to.shared.u64 t, %1; cvt.u32.u64 %0, t; }"
        : "=r"(a) : "l"(p));
    return a;
}
__device__ __forceinline__ unsigned f2tf32(float f) {
    unsigned r;
    asm("cvt.rna.tf32.f32 %0, %1;" : "=r"(r) : "f"(f));
    return r;
}
__device__ __forceinline__ void cp16(unsigned saddr, const float* g) {
    asm volatile("cp.async.cg.shared.global [%0], [%1], 16;"
                 :: "r"(saddr), "l"(g) : "memory");
}
__device__ __forceinline__ void mma_tf32(float* d, const unsigned* a, const unsigned* b) {
    asm volatile(
        "mma.sync.aligned.m16n8k8.row.col.f32.tf32.tf32.f32 "
        "{%0,%1,%2,%3}, {%4,%5,%6,%7}, {%8,%9}, {%0,%1,%2,%3};"
        : "+f"(d[0]), "+f"(d[1]), "+f"(d[2]), "+f"(d[3])
        : "r"(a[0]), "r"(a[1]), "r"(a[2]), "r"(a[3]), "r"(b[0]), "r"(b[1]));
}

// ---------------- zero counters ----------------
__global__ void zero_kernel() {
    int i = threadIdx.x;
    if (i < Ee) g_cnt[i] = 0;
}

// ---------------- router: 1 warp per token ----------------
__global__ void router_kernel(const float* __restrict__ x,
                              const float* __restrict__ rw) {
    int tid = threadIdx.x;
    int warp = tid >> 5, lane = tid & 31;
    int t = blockIdx.x * 8 + warp;

    const float* xr = x + (size_t)t * Dd;
    float acc[Ee];
#pragma unroll
    for (int e = 0; e < Ee; e++) acc[e] = 0.f;
    for (int d = lane; d < Dd; d += 32) {
        float xv = xr[d];
#pragma unroll
        for (int e = 0; e < Ee; e++) acc[e] += xv * rw[e * Dd + d];
    }
#pragma unroll
    for (int e = 0; e < Ee; e++)
#pragma unroll
        for (int off = 16; off > 0; off >>= 1)
            acc[e] += __shfl_xor_sync(0xffffffffu, acc[e], off);

    if (lane == 0) {
        float mx = acc[0];
#pragma unroll
        for (int e = 1; e < Ee; e++) mx = fmaxf(mx, acc[e]);
        float pe[Ee], s = 0.f;
#pragma unroll
        for (int e = 0; e < Ee; e++) { pe[e] = __expf(acc[e] - mx); s += pe[e]; }
        float inv = 1.f / s;
#pragma unroll
        for (int e = 0; e < Ee; e++) { pe[e] *= inv; g_probs[t * Ee + e] = pe[e]; }
        int i1 = 0;
#pragma unroll
        for (int e = 1; e < Ee; e++) if (pe[e] > pe[i1]) i1 = e;
        int i2 = (i1 == 0) ? 1 : 0;
#pragma unroll
        for (int e = 0; e < Ee; e++) if (e != i1 && pe[e] > pe[i2]) i2 = e;
        float denom = pe[i1] + pe[i2] + 1e-8f;
        int p1 = atomicAdd(&g_cnt[i1], 1);
        g_slot[i1 * Tt + p1] = t * 2 + 0;
        g_wt[t * 2 + 0] = pe[i1] / denom;
        int p2 = atomicAdd(&g_cnt[i2], 1);
        g_slot[i2 * Tt + p2] = t * 2 + 1;
        g_wt[t * 2 + 1] = pe[i2] / denom;
    }
}

// ---------------- tf32 mma.sync grouped GEMM ----------------
// CTA tile 128x128, K-chunk 32, 8 warps (2x4), warp tile 64x32.
// Double-buffered cp.async. A rows gathered via slot list.
// Smem: A [128][36] (bank = 4g+c, conflict-free), B [32][136] (bank = 8c+g).
#define A_PAD 36
#define B_PAD 136
#define A_SZ (128 * A_PAD)              // floats per A buffer
#define B_SZ (32 * B_PAD)               // floats per B buffer
#define SM_A0 0
#define SM_A1 (A_SZ)
#define SM_B0 (2 * A_SZ)
#define SM_B1 (2 * A_SZ + B_SZ)
#define SM_SLOT (2 * A_SZ + 2 * B_SZ)   // 128 ints
#define SMEM_FLOATS (SM_SLOT + 128)
#define SMEM_BYTES (SMEM_FLOATS * 4)

template<int LDA, int LDW, int KTOT, int NTOT, int SHIFT, bool GELU, int LDO>
__global__ __launch_bounds__(256, 2)
void mma_gemm(const float* __restrict__ Ain, const float* __restrict__ W,
              const float* __restrict__ bias) {
    const int e = blockIdx.z;
    const int ne = g_cnt[e];
    const int row0 = blockIdx.x * 128;
    if (row0 >= ne) return;
    const int n0 = blockIdx.y * 128;

    extern __shared__ __align__(16) float smem[];
    int* slot_s = (int*)(smem + SM_SLOT);

    const int tid = threadIdx.x, wid = tid >> 5, lane = tid & 31;
    const int g = lane >> 2, c = lane & 3;

    const float* A = (SHIFT == 1) ? Ain : (const float*)g_h;
    float* OUT = GELU ? (float*)g_h : (float*)g_y;

    if (tid < 128) {
        int r = row0 + tid;
        slot_s[tid] = g_slot[e * Tt + ((r < ne) ? r : (ne - 1))];
    }
    __syncthreads();

    // per-thread cp.async source/dest mapping
    const float* aRow = A + (size_t)(slot_s[tid >> 1] >> SHIFT) * LDA + (tid & 1) * 16;
    const float* bRow = W + (size_t)e * KTOT * LDW + (size_t)(tid >> 3) * LDW + n0 + (tid & 7) * 16;
    const unsigned dA = smem_u32(smem) + ((tid >> 1) * A_PAD + (tid & 1) * 16) * 4;
    const unsigned dB = smem_u32(smem) + (SM_B0 + (tid >> 3) * B_PAD + (tid & 7) * 16) * 4;

    const int NK = KTOT / 32;

    // prefetch chunk 0 into buffer 0
    {
#pragma unroll
        for (int q = 0; q < 4; q++) cp16(dA + q * 16, aRow + q * 4);
#pragma unroll
        for (int q = 0; q < 4; q++) cp16(dB + q * 16, bRow + q * 4);
        asm volatile("cp.async.commit_group;" ::: "memory");
    }

    const int wm = (wid >> 2) * 64;
    const int wn = (wid & 3) * 32;

    float acc[4][4][4];
#pragma unroll
    for (int mf = 0; mf < 4; mf++)
#pragma unroll
        for (int nf = 0; nf < 4; nf++)
#pragma unroll
            for (int v = 0; v < 4; v++) acc[mf][nf][v] = 0.f;

    for (int i = 0; i < NK; i++) {
        if (i + 1 < NK) {
            const int nb = (i + 1) & 1;
            const float* ap = aRow + (i + 1) * 32;
            const float* bp = bRow + (size_t)(i + 1) * 32 * LDW;
            const unsigned da = dA + nb * (A_SZ * 4);
            const unsigned db = dB + nb * (B_SZ * 4);
#pragma unroll
            for (int q = 0; q < 4; q++) cp16(da + q * 16, ap + q * 4);
#pragma unroll
            for (int q = 0; q < 4; q++) cp16(db + q * 16, bp + q * 4);
            asm volatile("cp.async.commit_group;" ::: "memory");
            asm volatile("cp.async.wait_group 1;" ::: "memory");
        } else {
            asm volatile("cp.async.wait_group 0;" ::: "memory");
        }
        __syncthreads();

        const float* AsB = smem + ((i & 1) ? SM_A1 : SM_A0);
        const float* BsB = smem + ((i & 1) ? SM_B1 : SM_B0);

#pragma unroll
        for (int kk = 0; kk < 4; kk++) {
            const int kb = kk * 8;
            unsigned a[4][4], b[4][2];
#pragma unroll
            for (int mf = 0; mf < 4; mf++) {
                const float* p = AsB + (wm + mf * 16 + g) * A_PAD + kb + c;
                a[mf][0] = f2tf32(p[0]);
                a[mf][1] = f2tf32(p[8 * A_PAD]);
                a[mf][2] = f2tf32(p[4]);
                a[mf][3] = f2tf32(p[8 * A_PAD + 4]);
            }
#pragma unroll
            for (int nf = 0; nf < 4; nf++) {
                const float* p = BsB + (kb + c) * B_PAD + wn + nf * 8 + g;
                b[nf][0] = f2tf32(p[0]);
                b[nf][1] = f2tf32(p[4 * B_PAD]);
            }
#pragma unroll
            for (int mf = 0; mf < 4; mf++)
#pragma unroll
                for (int nf = 0; nf < 4; nf++)
                    mma_tf32(acc[mf][nf], a[mf], b[nf]);
        }
        __syncthreads();
    }

    // ---------------- epilogue ----------------
#pragma unroll
    for (int mf = 0; mf < 4; mf++) {
        const int r0 = wm + mf * 16 + g;   // local rows r0 and r0+8
#pragma unroll
        for (int half = 0; half < 2; half++) {
            const int r = r0 + half * 8;
            if (row0 + r >= ne) continue;
            float* orow = OUT + (size_t)slot_s[r] * LDO + n0;
#pragma unroll
            for (int nf = 0; nf < 4; nf++) {
                const int col = wn + nf * 8 + c * 2;
                float v0 = acc[mf][nf][half * 2 + 0] + bias[e * NTOT + n0 + col];
                float v1 = acc[mf][nf][half * 2 + 1] + bias[e * NTOT + n0 + col + 1];
                if (GELU) {
                    v0 = 0.5f * v0 * (1.f + erff(v0 * 0.70710678118654752440f));
                    v1 = 0.5f * v1 * (1.f + erff(v1 * 0.70710678118654752440f));
                }
                float2 o; o.x = v0; o.y = v1;
                *(float2*)(orow + col) = o;
            }
        }
    }
}

// ---------------- combine ----------------
__global__ void combine_kernel(float* __restrict__ out) {
    int i = blockIdx.x * blockDim.x + threadIdx.x;
    int t = i >> 8;
    int d4 = i & 255;
    float w0 = g_wt[2 * t], w1 = g_wt[2 * t + 1];
    const float4* y = (const float4*)g_y;
    float4 a = y[(size_t)(2 * t) * 256 + d4];
    float4 b = y[(size_t)(2 * t + 1) * 256 + d4];
    float4 o;
    o.x = w0 * a.x + w1 * b.x;
    o.y = w0 * a.y + w1 * b.y;
    o.z = w0 * a.z + w1 * b.z;
    o.w = w0 * a.w + w1 * b.w;
    ((float4*)out)[i] = o;
}

// ---------------- load-balancing loss ----------------
__global__ void loss_kernel(float* __restrict__ out, int write_loss) {
    __shared__ float sred[256 * Ee];
    int tid = threadIdx.x;
    float l[Ee];
#pragma unroll
    for (int e = 0; e < Ee; e++) l[e] = 0.f;
    for (int t = tid; t < Tt; t += 256)
#pragma unroll
        for (int e = 0; e < Ee; e++) l[e] += g_probs[t * Ee + e];
#pragma unroll
    for (int e = 0; e < Ee; e++) sred[tid * Ee + e] = l[e];
    __syncthreads();
    for (int s = 128; s > 0; s >>= 1) {
        if (tid < s)
#pragma unroll
            for (int e = 0; e < Ee; e++)
                sred[tid * Ee + e] += sred[(tid + s) * Ee + e];
        __syncthreads();
    }
    if (tid == 0 && write_loss) {
        float loss = 0.f;
        for (int e = 0; e < Ee; e++) {
            float mean_p = sred[e] / (float)Tt;
            float frac = (float)g_cnt[e] / (float)(Tt * Kk);
            loss += mean_p * frac;
        }
        out[(size_t)Tt * Dd] = loss * (float)Ee;
    }
}

// ---------------- launch ----------------
extern "C" void kernel_launch(void* const* d_in, const int* in_sizes, int n_in,
                              void* d_out, int out_size) {
    const float* x  = (const float*)d_in[0];
    const float* rw = (const float*)d_in[1];
    const float* w1 = (const float*)d_in[2];
    const float* b1 = (const float*)d_in[3];
    const float* w2 = (const float*)d_in[4];
    const float* b2 = (const float*)d_in[5];
    float* out = (float*)d_out;

    cudaFuncSetAttribute(mma_gemm<Dd, Hh, Dd, Hh, 1, true, Hh>,
                         cudaFuncAttributeMaxDynamicSharedMemorySize, SMEM_BYTES);
    cudaFuncSetAttribute(mma_gemm<Hh, Dd, Hh, Dd, 0, false, Dd>,
                         cudaFuncAttributeMaxDynamicSharedMemorySize, SMEM_BYTES);

    zero_kernel<<<1, 32>>>();
    router_kernel<<<Tt / 8, 256>>>(x, rw);

    dim3 g1(Tt / 128, Hh / 128, Ee);
    mma_gemm<Dd, Hh, Dd, Hh, 1, true, Hh><<<g1, 256, SMEM_BYTES>>>(x, w1, b1);

    dim3 g2(Tt / 128, Dd / 128, Ee);
    mma_gemm<Hh, Dd, Hh, Dd, 0, false, Dd><<<g2, 256, SMEM_BYTES>>>(nullptr, w2, b2);

    combine_kernel<<<(Tt * Dd / 4) / 256, 256>>>(out);

    int write_loss = (out_size > Tt * Dd) ? 1 : 0;
    loss_kernel<<<1, 256>>>(out, write_loss);
}

// round 9
// speedup vs baseline: 4.0795x; 1.8857x over previous
#include <cuda_runtime.h>
#include <cuda_fp16.h>
#include <math.h>

#define Tt 4096
#define Dd 1024
#define Hh 4096
#define Ee 8
#define Kk 2

// ---------------- device scratch ----------------
__device__ int    g_cnt[Ee];
__device__ int    g_slot[Ee * Tt];
__device__ float  g_wt[Tt * Kk];
__device__ float  g_probs[Tt * Ee];
__device__ __half g_xh[(size_t)Tt * Dd];          // x in fp16
__device__ __half g_w1h[(size_t)Ee * Dd * Hh];    // w1 in fp16
__device__ __half g_w2h[(size_t)Ee * Hh * Dd];    // w2 in fp16
__device__ __half g_h[(size_t)Tt * Kk * Hh];      // gelu(x@w1+b1) per slot (fp16)
__device__ float  g_y[(size_t)Tt * Kk * Dd];      // (h@w2+b2) per slot (fp32)

// ---------------- helpers ----------------
__device__ __forceinline__ unsigned smem_u32(const void* p) {
    unsigned a;
    asm("{ .reg .u64 t; cvta.to.shared.u64 t, %1; cvt.u32.u64 %0, t; }"
        : "=r"(a) : "l"(p));
    return a;
}
__device__ __forceinline__ void cp16(unsigned saddr, const void* g) {
    asm volatile("cp.async.cg.shared.global [%0], [%1], 16;"
                 :: "r"(saddr), "l"(g) : "memory");
}
__device__ __forceinline__ void mma_f16(float* d, const unsigned* a, const unsigned* b) {
    asm volatile(
        "mma.sync.aligned.m16n8k16.row.col.f32.f16.f16.f32 "
        "{%0,%1,%2,%3}, {%4,%5,%6,%7}, {%8,%9}, {%0,%1,%2,%3};"
        : "+f"(d[0]), "+f"(d[1]), "+f"(d[2]), "+f"(d[3])
        : "r"(a[0]), "r"(a[1]), "r"(a[2]), "r"(a[3]), "r"(b[0]), "r"(b[1]));
}
#define LDSM_X4(r, addr) \
    asm volatile("ldmatrix.sync.aligned.m8n8.x4.shared.b16 {%0,%1,%2,%3}, [%4];" \
        : "=r"((r)[0]), "=r"((r)[1]), "=r"((r)[2]), "=r"((r)[3]) : "r"(addr))
#define LDSM_X4_T(r, addr) \
    asm volatile("ldmatrix.sync.aligned.m8n8.x4.trans.shared.b16 {%0,%1,%2,%3}, [%4];" \
        : "=r"((r)[0]), "=r"((r)[1]), "=r"((r)[2]), "=r"((r)[3]) : "r"(addr))

// ---------------- zero counters ----------------
__global__ void zero_kernel() {
    int i = threadIdx.x;
    if (i < Ee) g_cnt[i] = 0;
}

// ---------------- f32 -> f16 convert (8 elems/thread) ----------------
__global__ void f2h_kernel(const float* __restrict__ s, int which, int n) {
    __half* d = (which == 0) ? g_xh : (which == 1) ? g_w1h : g_w2h;
    size_t i = ((size_t)blockIdx.x * blockDim.x + threadIdx.x) * 8;
    if (i >= (size_t)n) return;
    float4 v0 = *(const float4*)(s + i);
    float4 v1 = *(const float4*)(s + i + 4);
    __half2 h0 = __floats2half2_rn(v0.x, v0.y);
    __half2 h1 = __floats2half2_rn(v0.z, v0.w);
    __half2 h2 = __floats2half2_rn(v1.x, v1.y);
    __half2 h3 = __floats2half2_rn(v1.z, v1.w);
    uint4 o;
    o.x = *(unsigned*)&h0; o.y = *(unsigned*)&h1;
    o.z = *(unsigned*)&h2; o.w = *(unsigned*)&h3;
    *(uint4*)(d + i) = o;
}

// ---------------- router: 1 warp per token ----------------
__global__ void router_kernel(const float* __restrict__ x,
                              const float* __restrict__ rw) {
    int tid = threadIdx.x;
    int warp = tid >> 5, lane = tid & 31;
    int t = blockIdx.x * 8 + warp;

    const float* xr = x + (size_t)t * Dd;
    float acc[Ee];
#pragma unroll
    for (int e = 0; e < Ee; e++) acc[e] = 0.f;
    for (int d = lane; d < Dd; d += 32) {
        float xv = xr[d];
#pragma unroll
        for (int e = 0; e < Ee; e++) acc[e] += xv * rw[e * Dd + d];
    }
#pragma unroll
    for (int e = 0; e < Ee; e++)
#pragma unroll
        for (int off = 16; off > 0; off >>= 1)
            acc[e] += __shfl_xor_sync(0xffffffffu, acc[e], off);

    if (lane == 0) {
        float mx = acc[0];
#pragma unroll
        for (int e = 1; e < Ee; e++) mx = fmaxf(mx, acc[e]);
        float pe[Ee], s = 0.f;
#pragma unroll
        for (int e = 0; e < Ee; e++) { pe[e] = __expf(acc[e] - mx); s += pe[e]; }
        float inv = 1.f / s;
#pragma unroll
        for (int e = 0; e < Ee; e++) { pe[e] *= inv; g_probs[t * Ee + e] = pe[e]; }
        int i1 = 0;
#pragma unroll
        for (int e = 1; e < Ee; e++) if (pe[e] > pe[i1]) i1 = e;
        int i2 = (i1 == 0) ? 1 : 0;
#pragma unroll
        for (int e = 0; e < Ee; e++) if (e != i1 && pe[e] > pe[i2]) i2 = e;
        float denom = pe[i1] + pe[i2] + 1e-8f;
        int p1 = atomicAdd(&g_cnt[i1], 1);
        g_slot[i1 * Tt + p1] = t * 2 + 0;
        g_wt[t * 2 + 0] = pe[i1] / denom;
        int p2 = atomicAdd(&g_cnt[i2], 1);
        g_slot[i2 * Tt + p2] = t * 2 + 1;
        g_wt[t * 2 + 1] = pe[i2] / denom;
    }
}

// ---------------- fp16 mma.sync grouped GEMM ----------------
// CTA tile 128x128, K-chunk 64 halves, 8 warps (2x4), warp tile 64x32.
// Double-buffered cp.async; ldmatrix fragments; gathered A rows.
// A smem: 128 rows x 144B stride (64 halves data). B smem: 64 rows x 272B (128 halves).
#define BK 64
#define A_BUF_B (128 * 144)              // 18432 bytes per A buffer
#define B_BUF_B (64 * 272)               // 17408 bytes per B buffer
#define SM_B0B (2 * A_BUF_B)             // 36864
#define SM_SLOT_B (2 * A_BUF_B + 2 * B_BUF_B)  // 71680
#define SMEM_BYTES (SM_SLOT_B + 512)     // 72192

template<int LDA, int LDW, int KTOT, int NTOT, int SHIFT, bool GELU, int LDO>
__global__ __launch_bounds__(256, 2)
void mma_gemm(const float* __restrict__ bias) {
    const int e = blockIdx.z;
    const int ne = g_cnt[e];
    const int row0 = blockIdx.x * 128;
    if (row0 >= ne) return;
    const int n0 = blockIdx.y * 128;

    extern __shared__ __align__(16) char smem[];
    int* slot_s = (int*)(smem + SM_SLOT_B);
    const unsigned sb = smem_u32(smem);

    const int tid = threadIdx.x, wid = tid >> 5, lane = tid & 31;
    const int g = lane >> 2, c = lane & 3;

    const __half* A = SHIFT ? g_xh : g_h;
    const __half* W = GELU ? g_w1h : g_w2h;

    if (tid < 128) {
        int r = row0 + tid;
        slot_s[tid] = g_slot[e * Tt + ((r < ne) ? r : (ne - 1))];
    }
    __syncthreads();

    // cp.async mappings: A 2 thr/row (4x16B each), B 4 thr/row (4x16B each)
    const int arow = tid >> 1, acb = (tid & 1) * 4;
    const __half* aSrc = A + (size_t)(slot_s[arow] >> SHIFT) * LDA + acb * 8;
    const unsigned aDst = sb + arow * 144 + acb * 16;
    const int brow = tid >> 2, bcb = (tid & 3) * 4;
    const __half* bSrc = W + (size_t)e * KTOT * LDW + (size_t)brow * LDW + n0 + bcb * 8;
    const unsigned bDst = sb + SM_B0B + brow * 272 + bcb * 16;

    const int NK = KTOT / BK;

    // prefetch chunk 0 into buffer 0
#pragma unroll
    for (int q = 0; q < 4; q++) cp16(aDst + q * 16, aSrc + q * 8);
#pragma unroll
    for (int q = 0; q < 4; q++) cp16(bDst + q * 16, bSrc + q * 8);
    asm volatile("cp.async.commit_group;" ::: "memory");

    const int wm = (wid >> 2) * 64;
    const int wn = (wid & 3) * 32;

    // ldmatrix lane address bases
    const unsigned aLd = sb + (wm + (lane & 15)) * 144 + (lane >> 4) * 16;
    const unsigned bLd = sb + SM_B0B + (lane & 15) * 272 + wn * 2 + (lane >> 4) * 16;

    float acc[4][4][4];
#pragma unroll
    for (int mf = 0; mf < 4; mf++)
#pragma unroll
        for (int nf = 0; nf < 4; nf++)
#pragma unroll
            for (int v = 0; v < 4; v++) acc[mf][nf][v] = 0.f;

    for (int i = 0; i < NK; i++) {
        if (i + 1 < NK) {
            const int nb = (i + 1) & 1;
            const __half* ap = aSrc + (i + 1) * BK;
            const __half* bp = bSrc + (size_t)(i + 1) * BK * LDW;
            const unsigned da = aDst + nb * A_BUF_B;
            const unsigned db = bDst + nb * B_BUF_B;
#pragma unroll
            for (int q = 0; q < 4; q++) cp16(da + q * 16, ap + q * 8);
#pragma unroll
            for (int q = 0; q < 4; q++) cp16(db + q * 16, bp + q * 8);
            asm volatile("cp.async.commit_group;" ::: "memory");
            asm volatile("cp.async.wait_group 1;" ::: "memory");
        } else {
            asm volatile("cp.async.wait_group 0;" ::: "memory");
        }
        __syncthreads();

        const unsigned aB = aLd + (i & 1) * A_BUF_B;
        const unsigned bB = bLd + (i & 1) * B_BUF_B;

#pragma unroll
        for (int ks = 0; ks < 4; ks++) {
            unsigned a[4][4], bb[2][4];
#pragma unroll
            for (int mf = 0; mf < 4; mf++)
                LDSM_X4(a[mf], aB + mf * (16 * 144) + ks * 32);
            LDSM_X4_T(bb[0], bB + ks * (16 * 272));
            LDSM_X4_T(bb[1], bB + ks * (16 * 272) + 32);
#pragma unroll
            for (int mf = 0; mf < 4; mf++)
#pragma unroll
                for (int nf = 0; nf < 4; nf++)
                    mma_f16(acc[mf][nf], a[mf], &bb[nf >> 1][(nf & 1) * 2]);
        }
        __syncthreads();
    }

    // ---------------- epilogue ----------------
#pragma unroll
    for (int mf = 0; mf < 4; mf++) {
#pragma unroll
        for (int half_i = 0; half_i < 2; half_i++) {
            const int r = wm + mf * 16 + g + half_i * 8;
            if (row0 + r >= ne) continue;
            const int s = slot_s[r];
#pragma unroll
            for (int nf = 0; nf < 4; nf++) {
                const int col = wn + nf * 8 + c * 2;
                float v0 = acc[mf][nf][half_i * 2 + 0] + bias[e * NTOT + n0 + col];
                float v1 = acc[mf][nf][half_i * 2 + 1] + bias[e * NTOT + n0 + col + 1];
                if (GELU) {
                    v0 = 0.5f * v0 * (1.f + erff(v0 * 0.70710678118654752440f));
                    v1 = 0.5f * v1 * (1.f + erff(v1 * 0.70710678118654752440f));
                    __half2 h2 = __floats2half2_rn(v0, v1);
                    *(__half2*)(g_h + (size_t)s * LDO + n0 + col) = h2;
                } else {
                    float2 o; o.x = v0; o.y = v1;
                    *(float2*)(g_y + (size_t)s * LDO + n0 + col) = o;
                }
            }
        }
    }
}

// ---------------- combine ----------------
__global__ void combine_kernel(float* __restrict__ out) {
    int i = blockIdx.x * blockDim.x + threadIdx.x;
    int t = i >> 8;
    int d4 = i & 255;
    float w0 = g_wt[2 * t], w1 = g_wt[2 * t + 1];
    const float4* y = (const float4*)g_y;
    float4 a = y[(size_t)(2 * t) * 256 + d4];
    float4 b = y[(size_t)(2 * t + 1) * 256 + d4];
    float4 o;
    o.x = w0 * a.x + w1 * b.x;
    o.y = w0 * a.y + w1 * b.y;
    o.z = w0 * a.z + w1 * b.z;
    o.w = w0 * a.w + w1 * b.w;
    ((float4*)out)[i] = o;
}

// ---------------- load-balancing loss ----------------
__global__ void loss_kernel(float* __restrict__ out, int write_loss) {
    __shared__ float sred[256 * Ee];
    int tid = threadIdx.x;
    float l[Ee];
#pragma unroll
    for (int e = 0; e < Ee; e++) l[e] = 0.f;
    for (int t = tid; t < Tt; t += 256)
#pragma unroll
        for (int e = 0; e < Ee; e++) l[e] += g_probs[t * Ee + e];
#pragma unroll
    for (int e = 0; e < Ee; e++) sred[tid * Ee + e] = l[e];
    __syncthreads();
    for (int s = 128; s > 0; s >>= 1) {
        if (tid < s)
#pragma unroll
            for (int e = 0; e < Ee; e++)
                sred[tid * Ee + e] += sred[(tid + s) * Ee + e];
        __syncthreads();
    }
    if (tid == 0 && write_loss) {
        float loss = 0.f;
        for (int e = 0; e < Ee; e++) {
            float mean_p = sred[e] / (float)Tt;
            float frac = (float)g_cnt[e] / (float)(Tt * Kk);
            loss += mean_p * frac;
        }
        out[(size_t)Tt * Dd] = loss * (float)Ee;
    }
}

// ---------------- launch ----------------
extern "C" void kernel_launch(void* const* d_in, const int* in_sizes, int n_in,
                              void* d_out, int out_size) {
    const float* x  = (const float*)d_in[0];
    const float* rw = (const float*)d_in[1];
    const float* w1 = (const float*)d_in[2];
    const float* b1 = (const float*)d_in[3];
    const float* w2 = (const float*)d_in[4];
    const float* b2 = (const float*)d_in[5];
    float* out = (float*)d_out;

    cudaFuncSetAttribute(mma_gemm<Dd, Hh, Dd, Hh, 1, true, Hh>,
                         cudaFuncAttributeMaxDynamicSharedMemorySize, SMEM_BYTES);
    cudaFuncSetAttribute(mma_gemm<Hh, Dd, Hh, Dd, 0, false, Dd>,
                         cudaFuncAttributeMaxDynamicSharedMemorySize, SMEM_BYTES);

    zero_kernel<<<1, 32>>>();
    router_kernel<<<Tt / 8, 256>>>(x, rw);

    // f32 -> f16 conversions
    f2h_kernel<<<(Tt * Dd / 8 + 255) / 256, 256>>>(x, 0, Tt * Dd);
    f2h_kernel<<<(Ee * Dd * Hh / 8 + 255) / 256, 256>>>(w1, 1, Ee * Dd * Hh);
    f2h_kernel<<<(Ee * Hh * Dd / 8 + 255) / 256, 256>>>(w2, 2, Ee * Hh * Dd);

    dim3 g1(Tt / 128, Hh / 128, Ee);
    mma_gemm<Dd, Hh, Dd, Hh, 1, true, Hh><<<g1, 256, SMEM_BYTES>>>(b1);

    dim3 g2(Tt / 128, Dd / 128, Ee);
    mma_gemm<Hh, Dd, Hh, Dd, 0, false, Dd><<<g2, 256, SMEM_BYTES>>>(b2);

    combine_kernel<<<(Tt * Dd / 4) / 256, 256>>>(out);

    int write_loss = (out_size > Tt * Dd) ? 1 : 0;
    loss_kernel<<<1, 256>>>(out, write_loss);
}